// round 1
// baseline (speedup 1.0000x reference)
#include <cuda_runtime.h>
#include <math.h>

// Problem sizes
constexpr int B_  = 8;
constexpr int N_  = 512;
constexpr int M_  = 512;
constexpr int D_  = 512;
constexpr int ND_ = N_ + M_ - 1;   // 1023 anti-diagonals (k = 2 .. N+M)
constexpr float NEGL    = -1.0e9f;
constexpr float INV_LN2 = 1.44269504088896340736f;

// Scratch: per-cell softmax weights (wU, wL), diagonal-major.
// g_w[b][d][r] = weights of cell (i = r+1, j = d - r + 1), d = (i+j) - 2
__device__ float2 g_w[(size_t)B_ * ND_ * N_];

// ---------------------------------------------------------------------------
// fast MUFU intrinsics
// ---------------------------------------------------------------------------
__device__ __forceinline__ float ex2f_(float x) { float y; asm("ex2.approx.ftz.f32 %0, %1;" : "=f"(y) : "f"(x)); return y; }
__device__ __forceinline__ float lg2f_(float x) { float y; asm("lg2.approx.f32 %0, %1;"     : "=f"(y) : "f"(x)); return y; }
__device__ __forceinline__ float rcpf_(float x) { float y; asm("rcp.approx.f32 %0, %1;"     : "=f"(y) : "f"(x)); return y; }

// ---------------------------------------------------------------------------
// Fused GEMM + activation:
//   sel=0: out_theta[b] = softplus(zx[b] @ zy[b]^T)
//   sel=1: out_A[b]     = log_sigmoid(gx[b] @ gy[b]^T)
// 128x128 block tile, 256 threads, 8x8 per-thread micro tile, K-chunks of 16.
// ---------------------------------------------------------------------------
__global__ void __launch_bounds__(256, 2) gemm_act_kernel(
    const float* __restrict__ zx, const float* __restrict__ zy,
    const float* __restrict__ gx, const float* __restrict__ gy,
    float* __restrict__ out)
{
    const int mz  = blockIdx.z;
    const int b   = mz & 7;
    const int sel = mz >> 3;
    const float* X = (sel ? gx : zx) + (size_t)b * N_ * D_;
    const float* Y = (sel ? gy : zy) + (size_t)b * M_ * D_;
    float* C = out + (size_t)(1 + sel) * B_ * N_ * M_ + (size_t)b * N_ * M_;

    const int row0 = blockIdx.y * 128;
    const int col0 = blockIdx.x * 128;

    __shared__ float Xs[16][132];
    __shared__ float Ys[16][132];

    const int t  = threadIdx.x;
    const int lr = t >> 1;            // 0..127  (row within tile to load)
    const int lk = (t & 1) * 8;       // 0 or 8  (k offset to load)
    const int ty = t >> 4;            // 0..15
    const int tx = t & 15;            // 0..15

    float acc[8][8];
#pragma unroll
    for (int r = 0; r < 8; ++r)
#pragma unroll
        for (int c = 0; c < 8; ++c) acc[r][c] = 0.f;

    for (int k0 = 0; k0 < D_; k0 += 16) {
        // issue global loads early (overlap other warps' previous compute)
        const float4 xv0 = *(const float4*)(X + (size_t)(row0 + lr) * D_ + k0 + lk);
        const float4 xv1 = *(const float4*)(X + (size_t)(row0 + lr) * D_ + k0 + lk + 4);
        const float4 yv0 = *(const float4*)(Y + (size_t)(col0 + lr) * D_ + k0 + lk);
        const float4 yv1 = *(const float4*)(Y + (size_t)(col0 + lr) * D_ + k0 + lk + 4);
        __syncthreads();   // smem free (prev compute done everywhere)
        Xs[lk + 0][lr] = xv0.x; Xs[lk + 1][lr] = xv0.y; Xs[lk + 2][lr] = xv0.z; Xs[lk + 3][lr] = xv0.w;
        Xs[lk + 4][lr] = xv1.x; Xs[lk + 5][lr] = xv1.y; Xs[lk + 6][lr] = xv1.z; Xs[lk + 7][lr] = xv1.w;
        Ys[lk + 0][lr] = yv0.x; Ys[lk + 1][lr] = yv0.y; Ys[lk + 2][lr] = yv0.z; Ys[lk + 3][lr] = yv0.w;
        Ys[lk + 4][lr] = yv1.x; Ys[lk + 5][lr] = yv1.y; Ys[lk + 6][lr] = yv1.z; Ys[lk + 7][lr] = yv1.w;
        __syncthreads();
#pragma unroll
        for (int kk = 0; kk < 16; ++kk) {
            float a0[8], b0[8];
            *(float4*)(a0)     = *(const float4*)&Xs[kk][ty * 8];
            *(float4*)(a0 + 4) = *(const float4*)&Xs[kk][ty * 8 + 4];
            *(float4*)(b0)     = *(const float4*)&Ys[kk][tx * 8];
            *(float4*)(b0 + 4) = *(const float4*)&Ys[kk][tx * 8 + 4];
#pragma unroll
            for (int r = 0; r < 8; ++r)
#pragma unroll
                for (int c = 0; c < 8; ++c)
                    acc[r][c] = fmaf(a0[r], b0[c], acc[r][c]);
        }
    }

    // epilogue + activation
#pragma unroll
    for (int r = 0; r < 8; ++r) {
        const int row = row0 + ty * 8 + r;
#pragma unroll
        for (int c4 = 0; c4 < 8; c4 += 4) {
            float4 v;
            float* vp = &v.x;
#pragma unroll
            for (int q = 0; q < 4; ++q) {
                const float x = acc[r][c4 + q];
                const float l = log1pf(__expf(-fabsf(x)));
                vp[q] = sel ? (fminf(x, 0.f) - l)     // log_sigmoid
                            : (fmaxf(x, 0.f) + l);    // softplus
            }
            *(float4*)(C + (size_t)row * M_ + col0 + tx * 8 + c4) = v;
        }
    }
}

// ---------------------------------------------------------------------------
// Forward soft-NW (log2 domain). One block per batch, thread tid owns row
// i = tid+1. Anti-diagonal wavefront with 3 rotating shared diagonals.
// Stores softmax weights (wU, wL) per cell to g_w (wD = 1 - wU - wL).
// ---------------------------------------------------------------------------
__global__ void __launch_bounds__(512) nw_fwd_kernel(const float* __restrict__ out)
{
    const float* theta = out + (size_t)B_ * N_ * M_;
    const float* Ag    = out + (size_t)2 * B_ * N_ * M_;

    const int b = blockIdx.x, tid = threadIdx.x;

    __shared__ float s0[516], s1[516], s2[516];
    float* rows[3] = { s0, s1, s2 };
    for (int idx = tid; idx < 516; idx += 512) { s0[idx] = NEGL; s1[idx] = NEGL; s2[idx] = NEGL; }
    __syncthreads();
    if (tid == 0) s0[0] = 0.f;   // diag k=0: V[0,0] = 0   (rows[(2+1)%3] = s0 = p2 at k=2)
    __syncthreads();

    const float* thRow = theta + ((size_t)b * N_ + tid) * M_;
    const float* aRow  = Ag    + ((size_t)b * N_ + tid) * M_;
    float2* Wb = g_w + (size_t)b * ND_ * N_;

    // depth-2 prefetch queue for theta/A (column index j-1 = k - tid - 2, +1/iter)
    float th0 = 0.f, a0 = 0.f, th1 = 0.f, a1 = 0.f;
    {
        int c = 0 - tid;
        if ((unsigned)c < (unsigned)M_) { th0 = thRow[c] * INV_LN2; a0 = aRow[c] * INV_LN2; }
        c = 1 - tid;
        if ((unsigned)c < (unsigned)M_) { th1 = thRow[c] * INV_LN2; a1 = aRow[c] * INV_LN2; }
    }
    int pc = 2 - tid;

    for (int k = 2; k <= N_ + M_; ++k) {
        float thN = 0.f, aN = 0.f;
        if ((unsigned)pc < (unsigned)M_) { thN = thRow[pc] * INV_LN2; aN = aRow[pc] * INV_LN2; }
        ++pc;

        const float* p1 = rows[(k + 2) % 3];   // diag k-1
        const float* p2 = rows[(k + 1) % 3];   // diag k-2
        float*       cur = rows[k % 3];

        const float up = p1[tid];        // V[i-1, j]
        const float lf = p1[tid + 1];    // V[i,   j-1]
        const float dg = p2[tid];        // V[i-1, j-1]

        const float x0 = a0 + up;
        const float x1 = dg;
        const float x2 = a0 + lf;
        const float m  = fmaxf(x0, fmaxf(x1, x2));
        const float e0 = ex2f_(x0 - m);
        const float e1 = ex2f_(x1 - m);
        const float e2 = ex2f_(x2 - m);
        const float s  = e0 + e1 + e2;            // in [1, 3]
        const float r  = rcpf_(s);
        const float v  = th0 + m + lg2f_(s);

        const int  j     = k - tid - 1;
        const bool valid = (unsigned)(j - 1) < (unsigned)M_;
        cur[tid + 1] = valid ? v : NEGL;
        if (tid == 0) cur[0] = NEGL;              // keep top boundary -inf after rotation

        Wb[(size_t)(k - 2) * N_ + tid] = make_float2(e0 * r, e2 * r);

        th0 = th1; a0 = a1; th1 = thN; a1 = aN;
        __syncthreads();
    }
}

// ---------------------------------------------------------------------------
// Backward: E[i,j] = E[i+1,j]*wU(i+1,j) + E[i,j+1]*wL(i,j+1)
//                  + E[i+1,j+1]*(1 - wU - wL)(i+1,j+1),   E[N,M] = 1.
// aln[b][i-1][j-1] = E[i,j]. Zero-padded E diagonals make masking automatic.
// ---------------------------------------------------------------------------
__global__ void __launch_bounds__(512) nw_bwd_kernel(float* __restrict__ out)
{
    const int b = blockIdx.x, tid = threadIdx.x;

    __shared__ float s0[516], s1[516], s2[516];
    float* rows[3] = { s0, s1, s2 };
    for (int idx = tid; idx < 516; idx += 512) { s0[idx] = 0.f; s1[idx] = 0.f; s2[idx] = 0.f; }
    __syncthreads();

    const float2* Wb = g_w + (size_t)b * ND_ * N_;
    float* alnB = out + (size_t)b * N_ * M_;

    // weights needed at cell (i=tid+1, j=k-i):
    //   A = W[d=k-1][tid+1] -> cell (i+1, j)   (use .x = wU)
    //   Bq= W[d=k-1][tid]   -> cell (i,   j+1) (use .y = wL)
    //   C = W[d=k  ][tid+1] -> cell (i+1, j+1) (wD = 1 - .x - .y)
    auto load3 = [&](int k, float2& Aq, float2& Bq, float2& Cq) {
        Aq = make_float2(0.f, 0.f); Bq = Aq; Cq = Aq;
        if (k >= 2) {
            const int d1 = k - 1;
            if (d1 <= ND_ - 1) {
                const float2* p = Wb + (size_t)d1 * N_;
                Bq = p[tid];
                if (tid < N_ - 1) Aq = p[tid + 1];
            }
            if (k <= ND_ - 1 && tid < N_ - 1) Cq = Wb[(size_t)k * N_ + tid + 1];
        }
    };

    float2 A0, B0v, C0, A1, B1v, C1;
    load3(N_ + M_,     A0, B0v, C0);
    load3(N_ + M_ - 1, A1, B1v, C1);

    for (int k = N_ + M_; k >= 2; --k) {
        float2 A2, B2v, C2;
        load3(k - 2, A2, B2v, C2);   // depth-2 prefetch

        const float* n1 = rows[(k + 1) % 3];   // E diag k+1
        const float* n2 = rows[(k + 2) % 3];   // E diag k+2
        float*       cur = rows[k % 3];

        float e = n1[tid + 2] * A0.x
                + n1[tid + 1] * B0v.y
                + n2[tid + 2] * (1.f - C0.x - C0.y);
        if (k == N_ + M_) e = 1.f;             // base case E[N,M]

        const int  j     = k - tid - 1;
        const bool valid = (unsigned)(j - 1) < (unsigned)M_;
        cur[tid + 1] = valid ? e : 0.f;
        if (valid) alnB[(size_t)tid * M_ + (j - 1)] = e;

        A0 = A1; B0v = B1v; C0 = C1;
        A1 = A2; B1v = B2v; C1 = C2;
        __syncthreads();
    }
}

// ---------------------------------------------------------------------------
// launch
// ---------------------------------------------------------------------------
extern "C" void kernel_launch(void* const* d_in, const int* in_sizes, int n_in,
                              void* d_out, int out_size)
{
    const float* zx = (const float*)d_in[0];
    const float* zy = (const float*)d_in[1];
    const float* gx = (const float*)d_in[2];
    const float* gy = (const float*)d_in[3];
    float* out = (float*)d_out;   // [aln | theta | A], each B*N*M floats

    dim3 ggrid(M_ / 128, N_ / 128, 2 * B_);
    gemm_act_kernel<<<ggrid, 256>>>(zx, zy, gx, gy, out);
    nw_fwd_kernel<<<B_, 512>>>(out);
    nw_bwd_kernel<<<B_, 512>>>(out);
}

// round 2
// speedup vs baseline: 1.2910x; 1.2910x over previous
#include <cuda_runtime.h>
#include <math.h>

constexpr int B_  = 8;
constexpr int N_  = 512;
constexpr int M_  = 512;
constexpr int D_  = 512;
constexpr int ND_ = N_ + M_ - 1;   // 1023 anti-diagonals
constexpr float NEGL    = -1.0e9f;
constexpr float INV_LN2 = 1.44269504088896340736f;

// Diagonal-major scratch. g_tha[b][d][r] = (theta, A)/ln2 of cell (i=r+1, j=d-r+1).
// g_w: softmax weights (wU, wL); g_e: expected-alignment E values.
__device__ float2 g_tha[(size_t)B_ * ND_ * N_];
__device__ float2 g_w  [(size_t)B_ * ND_ * N_];
__device__ float  g_e  [(size_t)B_ * ND_ * N_];

__device__ __forceinline__ float ex2f_(float x) { float y; asm("ex2.approx.ftz.f32 %0, %1;" : "=f"(y) : "f"(x)); return y; }
__device__ __forceinline__ float lg2f_(float x) { float y; asm("lg2.approx.f32 %0, %1;"     : "=f"(y) : "f"(x)); return y; }
__device__ __forceinline__ float rcpf_(float x) { float y; asm("rcp.approx.f32 %0, %1;"     : "=f"(y) : "f"(x)); return y; }

// ---------------------------------------------------------------------------
// GEMM + activation (unchanged from R1): 128x128 tile, 256 thr, 8x8 micro.
// ---------------------------------------------------------------------------
__global__ void __launch_bounds__(256, 2) gemm_act_kernel(
    const float* __restrict__ zx, const float* __restrict__ zy,
    const float* __restrict__ gx, const float* __restrict__ gy,
    float* __restrict__ out)
{
    const int mz  = blockIdx.z;
    const int b   = mz & 7;
    const int sel = mz >> 3;
    const float* X = (sel ? gx : zx) + (size_t)b * N_ * D_;
    const float* Y = (sel ? gy : zy) + (size_t)b * M_ * D_;
    float* C = out + (size_t)(1 + sel) * B_ * N_ * M_ + (size_t)b * N_ * M_;

    const int row0 = blockIdx.y * 128;
    const int col0 = blockIdx.x * 128;

    __shared__ float Xs[16][132];
    __shared__ float Ys[16][132];

    const int t  = threadIdx.x;
    const int lr = t >> 1;
    const int lk = (t & 1) * 8;
    const int ty = t >> 4;
    const int tx = t & 15;

    float acc[8][8];
#pragma unroll
    for (int r = 0; r < 8; ++r)
#pragma unroll
        for (int c = 0; c < 8; ++c) acc[r][c] = 0.f;

    for (int k0 = 0; k0 < D_; k0 += 16) {
        const float4 xv0 = *(const float4*)(X + (size_t)(row0 + lr) * D_ + k0 + lk);
        const float4 xv1 = *(const float4*)(X + (size_t)(row0 + lr) * D_ + k0 + lk + 4);
        const float4 yv0 = *(const float4*)(Y + (size_t)(col0 + lr) * D_ + k0 + lk);
        const float4 yv1 = *(const float4*)(Y + (size_t)(col0 + lr) * D_ + k0 + lk + 4);
        __syncthreads();
        Xs[lk + 0][lr] = xv0.x; Xs[lk + 1][lr] = xv0.y; Xs[lk + 2][lr] = xv0.z; Xs[lk + 3][lr] = xv0.w;
        Xs[lk + 4][lr] = xv1.x; Xs[lk + 5][lr] = xv1.y; Xs[lk + 6][lr] = xv1.z; Xs[lk + 7][lr] = xv1.w;
        Ys[lk + 0][lr] = yv0.x; Ys[lk + 1][lr] = yv0.y; Ys[lk + 2][lr] = yv0.z; Ys[lk + 3][lr] = yv0.w;
        Ys[lk + 4][lr] = yv1.x; Ys[lk + 5][lr] = yv1.y; Ys[lk + 6][lr] = yv1.z; Ys[lk + 7][lr] = yv1.w;
        __syncthreads();
#pragma unroll
        for (int kk = 0; kk < 16; ++kk) {
            float a0[8], b0[8];
            *(float4*)(a0)     = *(const float4*)&Xs[kk][ty * 8];
            *(float4*)(a0 + 4) = *(const float4*)&Xs[kk][ty * 8 + 4];
            *(float4*)(b0)     = *(const float4*)&Ys[kk][tx * 8];
            *(float4*)(b0 + 4) = *(const float4*)&Ys[kk][tx * 8 + 4];
#pragma unroll
            for (int r = 0; r < 8; ++r)
#pragma unroll
                for (int c = 0; c < 8; ++c)
                    acc[r][c] = fmaf(a0[r], b0[c], acc[r][c]);
        }
    }

#pragma unroll
    for (int r = 0; r < 8; ++r) {
        const int row = row0 + ty * 8 + r;
#pragma unroll
        for (int c4 = 0; c4 < 8; c4 += 4) {
            float4 v;
            float* vp = &v.x;
#pragma unroll
            for (int q = 0; q < 4; ++q) {
                const float x = acc[r][c4 + q];
                const float l = log1pf(__expf(-fabsf(x)));
                vp[q] = sel ? (fminf(x, 0.f) - l)     // log_sigmoid
                            : (fmaxf(x, 0.f) + l);    // softplus
            }
            *(float4*)(C + (size_t)row * M_ + col0 + tx * 8 + c4) = v;
        }
    }
}

// ---------------------------------------------------------------------------
// Diagonalize: theta,A (row-major) -> g_tha (diag-major float2, pre-scaled).
// 32x32 tiles via smem (stride 32: diagonal access hits distinct banks).
// ---------------------------------------------------------------------------
__global__ void __launch_bounds__(256) diag_kernel(const float* __restrict__ out)
{
    const float* theta = out + (size_t)B_ * N_ * M_;
    const float* Ag    = out + (size_t)2 * B_ * N_ * M_;
    const int b  = blockIdx.z;
    const int i0 = blockIdx.y * 32;
    const int j0 = blockIdx.x * 32;

    __shared__ float sth[32 * 32];
    __shared__ float sa [32 * 32];

    const int t    = threadIdx.x;
    const int warp = t >> 5;
    const int lane = t & 31;

#pragma unroll
    for (int it = 0; it < 4; ++it) {
        const int r = warp + it * 8;
        const int c = lane;
        const size_t g = ((size_t)b * N_ + (i0 + r)) * M_ + (j0 + c);
        sth[r * 32 + c] = theta[g] * INV_LN2;
        sa [r * 32 + c] = Ag[g]    * INV_LN2;
    }
    __syncthreads();

    float2* dst = g_tha + (size_t)b * ND_ * N_;
#pragma unroll
    for (int dd0 = 0; dd0 < 64; dd0 += 8) {
        const int dd = dd0 + warp;
        const int il = lane;
        const int jl = dd - il;
        if ((unsigned)jl < 32u) {
            const int d = i0 + j0 + dd;
            dst[(size_t)d * N_ + (i0 + il)] = make_float2(sth[il * 32 + jl], sa[il * 32 + jl]);
        }
    }
}

// ---------------------------------------------------------------------------
// Undiagonalize: g_e (diag-major) -> aln (row-major).
// ---------------------------------------------------------------------------
__global__ void __launch_bounds__(256) undiag_kernel(float* __restrict__ out)
{
    const int b  = blockIdx.z;
    const int i0 = blockIdx.y * 32;
    const int j0 = blockIdx.x * 32;

    __shared__ float se[32 * 32];

    const int t    = threadIdx.x;
    const int warp = t >> 5;
    const int lane = t & 31;

    const float* src = g_e + (size_t)b * ND_ * N_;
#pragma unroll
    for (int dd0 = 0; dd0 < 64; dd0 += 8) {
        const int dd = dd0 + warp;
        const int il = lane;
        const int jl = dd - il;
        if ((unsigned)jl < 32u) {
            const int d = i0 + j0 + dd;
            se[il * 32 + jl] = src[(size_t)d * N_ + (i0 + il)];
        }
    }
    __syncthreads();

    float* alnB = out + (size_t)b * N_ * M_;
#pragma unroll
    for (int it = 0; it < 4; ++it) {
        const int r = warp + it * 8;
        const int c = lane;
        alnB[(size_t)(i0 + r) * M_ + (j0 + c)] = se[r * 32 + c];
    }
}

// ---------------------------------------------------------------------------
// Forward soft-NW (log2 domain), diag-major coalesced loads,
// whole-warp early-out outside the active band.
// ---------------------------------------------------------------------------
__global__ void __launch_bounds__(512) nw_fwd_kernel()
{
    const int b   = blockIdx.x;
    const int tid = threadIdx.x;
    const int w0  = tid & ~31;     // warp's base row

    __shared__ float s0[516], s1[516], s2[516];
    float* rows_[3] = { s0, s1, s2 };
    for (int idx = tid; idx < 516; idx += 512) { s0[idx] = NEGL; s1[idx] = NEGL; s2[idx] = NEGL; }
    __syncthreads();
    if (tid == 0) s0[0] = 0.f;     // V[0,0] = 0 (diag k=0 buffer)
    __syncthreads();

    const float2* THA = g_tha + (size_t)b * ND_ * N_;
    float2*       Wb  = g_w   + (size_t)b * ND_ * N_;

    // depth-2 prefetch of (theta, A) for diagonals d=0,1
    float2 t0 = make_float2(0.f, 0.f), t1 = t0;
    if ((unsigned)(0 - tid) < (unsigned)M_) t0 = THA[tid];
    if ((unsigned)(1 - tid) < (unsigned)M_) t1 = THA[(size_t)N_ + tid];

    for (int k = 2; k <= N_ + M_; ++k) {
        const int d = k - 2;
        float2 tn = make_float2(0.f, 0.f);
        {
            const int dn = d + 2;
            if (dn < ND_ && (unsigned)(dn - tid) < (unsigned)M_)
                tn = THA[(size_t)dn * N_ + tid];
        }
        const float* p1  = rows_[(k + 2) % 3];   // diag k-1
        const float* p2  = rows_[(k + 1) % 3];   // diag k-2
        float*       cur = rows_[k % 3];

        if (d >= w0 && d < w0 + 32 + M_ - 1) {   // warp intersects the band
            const float up = p1[tid];            // V[i-1, j]
            const float lf = p1[tid + 1];        // V[i,   j-1]
            const float dg = p2[tid];            // V[i-1, j-1]

            const float x0 = t0.y + up;
            const float x2 = t0.y + lf;
            const float m  = fmaxf(fmaxf(x0, x2), dg);
            const float e0 = ex2f_(x0 - m);
            const float e1 = ex2f_(dg - m);
            const float e2 = ex2f_(x2 - m);
            const float s  = e0 + e1 + e2;
            const float r  = rcpf_(s);
            const float v  = t0.x + m + lg2f_(s);

            const bool valid = (unsigned)(d - tid) < (unsigned)M_;
            cur[tid + 1] = valid ? v : NEGL;
            if (tid == 0) cur[0] = NEGL;
            if (valid) Wb[(size_t)d * N_ + tid] = make_float2(e0 * r, e2 * r);
        }
        t0 = t1; t1 = tn;
        __syncthreads();
    }
}

// ---------------------------------------------------------------------------
// Backward: E[i,j] = E[i+1,j]*wU(i+1,j) + E[i,j+1]*wL(i,j+1)
//                  + E[i+1,j+1]*(1-wU-wL)(i+1,j+1),  E[N,M]=1.
// Writes E diag-major (coalesced); undiag kernel produces aln.
// ---------------------------------------------------------------------------
__global__ void __launch_bounds__(512) nw_bwd_kernel()
{
    const int b   = blockIdx.x;
    const int tid = threadIdx.x;
    const int w0  = tid & ~31;

    __shared__ float s0[516], s1[516], s2[516];
    float* rows_[3] = { s0, s1, s2 };
    for (int idx = tid; idx < 516; idx += 512) { s0[idx] = 0.f; s1[idx] = 0.f; s2[idx] = 0.f; }
    __syncthreads();

    const float2* Wb = g_w + (size_t)b * ND_ * N_;
    float*        Eb = g_e + (size_t)b * ND_ * N_;

    // Weights needed at cell (i=tid+1, j=k-i):
    //   Aq = W[k-2+1][tid+1] -> child (i+1, j)    (.x = wU)
    //   Bq = W[k-2+1][tid]   -> child (i,   j+1)  (.y = wL)
    //   Cq = W[k-2+2][tid+1] -> child (i+1, j+1)  (wD = 1-.x-.y)
    auto load3 = [&](int k, float2& Aq, float2& Bq, float2& Cq) {
        Aq = make_float2(0.f, 0.f); Bq = Aq; Cq = Aq;
        if (k < 2) return;
        const int d = k - 2;
        const unsigned dmt  = (unsigned)(d - tid);
        const unsigned d1mt = (unsigned)(d + 1 - tid);
        if (d + 1 <= ND_ - 1) {
            const float2* p = Wb + (size_t)(d + 1) * N_;
            if (d1mt < (unsigned)M_) Bq = p[tid];                       // child (i, j+1) valid
            if (dmt  < (unsigned)M_ && tid < N_ - 1) Aq = p[tid + 1];   // child (i+1, j) valid
        }
        if (d + 2 <= ND_ - 1 && d1mt < (unsigned)M_ && tid < N_ - 1)
            Cq = Wb[(size_t)(d + 2) * N_ + tid + 1];                    // child (i+1, j+1) valid
    };

    float2 A0, B0v, C0, A1, B1v, C1;
    load3(N_ + M_,     A0, B0v, C0);
    load3(N_ + M_ - 1, A1, B1v, C1);

    for (int k = N_ + M_; k >= 2; --k) {
        const int d = k - 2;
        float2 A2, B2v, C2;
        load3(k - 2, A2, B2v, C2);   // depth-2 prefetch

        const float* n1  = rows_[(k + 1) % 3];   // E diag k+1
        const float* n2  = rows_[(k + 2) % 3];   // E diag k+2
        float*       cur = rows_[k % 3];

        if (d >= w0 && d < w0 + 32 + M_ - 1) {
            float e = n1[tid + 2] * A0.x
                    + n1[tid + 1] * B0v.y
                    + n2[tid + 2] * (1.f - C0.x - C0.y);
            if (k == N_ + M_) e = 1.f;           // base case E[N,M]

            const bool valid = (unsigned)(d - tid) < (unsigned)M_;
            cur[tid + 1] = valid ? e : 0.f;
            if (valid) Eb[(size_t)d * N_ + tid] = e;
        }
        A0 = A1; B0v = B1v; C0 = C1;
        A1 = A2; B1v = B2v; C1 = C2;
        __syncthreads();
    }
}

// ---------------------------------------------------------------------------
// launch
// ---------------------------------------------------------------------------
extern "C" void kernel_launch(void* const* d_in, const int* in_sizes, int n_in,
                              void* d_out, int out_size)
{
    const float* zx = (const float*)d_in[0];
    const float* zy = (const float*)d_in[1];
    const float* gx = (const float*)d_in[2];
    const float* gy = (const float*)d_in[3];
    float* out = (float*)d_out;   // [aln | theta | A]

    dim3 ggrid(M_ / 128, N_ / 128, 2 * B_);
    gemm_act_kernel<<<ggrid, 256>>>(zx, zy, gx, gy, out);

    dim3 tgrid(M_ / 32, N_ / 32, B_);
    diag_kernel<<<tgrid, 256>>>(out);
    nw_fwd_kernel<<<B_, 512>>>();
    nw_bwd_kernel<<<B_, 512>>>();
    undiag_kernel<<<tgrid, 256>>>(out);
}

// round 3
// speedup vs baseline: 1.4335x; 1.1104x over previous
#include <cuda_runtime.h>
#include <math.h>

constexpr int B_  = 8;
constexpr int N_  = 512;
constexpr int M_  = 512;
constexpr int D_  = 512;
constexpr int ND_ = N_ + M_ - 1;   // 1023 anti-diagonals
constexpr float NEGL    = -1.0e9f;
constexpr float INV_LN2 = 1.44269504088896340736f;

// Diagonal-major scratch (zero-initialized; invalid slots are never written,
// so they stay zero forever — bwd relies on this for implicit masking).
__device__ float2 g_tha[(size_t)B_ * ND_ * N_];
__device__ float2 g_w  [(size_t)B_ * ND_ * N_];
__device__ float  g_e  [(size_t)B_ * ND_ * N_];

__device__ __forceinline__ float ex2f_(float x) { float y; asm("ex2.approx.ftz.f32 %0, %1;" : "=f"(y) : "f"(x)); return y; }
__device__ __forceinline__ float lg2f_(float x) { float y; asm("lg2.approx.f32 %0, %1;"     : "=f"(y) : "f"(x)); return y; }
__device__ __forceinline__ float rcpf_(float x) { float y; asm("rcp.approx.f32 %0, %1;"     : "=f"(y) : "f"(x)); return y; }

// ---------------------------------------------------------------------------
// GEMM + activation (unchanged): 128x128 tile, 256 thr, 8x8 micro.
// ---------------------------------------------------------------------------
__global__ void __launch_bounds__(256, 2) gemm_act_kernel(
    const float* __restrict__ zx, const float* __restrict__ zy,
    const float* __restrict__ gx, const float* __restrict__ gy,
    float* __restrict__ out)
{
    const int mz  = blockIdx.z;
    const int b   = mz & 7;
    const int sel = mz >> 3;
    const float* X = (sel ? gx : zx) + (size_t)b * N_ * D_;
    const float* Y = (sel ? gy : zy) + (size_t)b * M_ * D_;
    float* C = out + (size_t)(1 + sel) * B_ * N_ * M_ + (size_t)b * N_ * M_;

    const int row0 = blockIdx.y * 128;
    const int col0 = blockIdx.x * 128;

    __shared__ float Xs[16][132];
    __shared__ float Ys[16][132];

    const int t  = threadIdx.x;
    const int lr = t >> 1;
    const int lk = (t & 1) * 8;
    const int ty = t >> 4;
    const int tx = t & 15;

    float acc[8][8];
#pragma unroll
    for (int r = 0; r < 8; ++r)
#pragma unroll
        for (int c = 0; c < 8; ++c) acc[r][c] = 0.f;

    for (int k0 = 0; k0 < D_; k0 += 16) {
        const float4 xv0 = *(const float4*)(X + (size_t)(row0 + lr) * D_ + k0 + lk);
        const float4 xv1 = *(const float4*)(X + (size_t)(row0 + lr) * D_ + k0 + lk + 4);
        const float4 yv0 = *(const float4*)(Y + (size_t)(col0 + lr) * D_ + k0 + lk);
        const float4 yv1 = *(const float4*)(Y + (size_t)(col0 + lr) * D_ + k0 + lk + 4);
        __syncthreads();
        Xs[lk + 0][lr] = xv0.x; Xs[lk + 1][lr] = xv0.y; Xs[lk + 2][lr] = xv0.z; Xs[lk + 3][lr] = xv0.w;
        Xs[lk + 4][lr] = xv1.x; Xs[lk + 5][lr] = xv1.y; Xs[lk + 6][lr] = xv1.z; Xs[lk + 7][lr] = xv1.w;
        Ys[lk + 0][lr] = yv0.x; Ys[lk + 1][lr] = yv0.y; Ys[lk + 2][lr] = yv0.z; Ys[lk + 3][lr] = yv0.w;
        Ys[lk + 4][lr] = yv1.x; Ys[lk + 5][lr] = yv1.y; Ys[lk + 6][lr] = yv1.z; Ys[lk + 7][lr] = yv1.w;
        __syncthreads();
#pragma unroll
        for (int kk = 0; kk < 16; ++kk) {
            float a0[8], b0[8];
            *(float4*)(a0)     = *(const float4*)&Xs[kk][ty * 8];
            *(float4*)(a0 + 4) = *(const float4*)&Xs[kk][ty * 8 + 4];
            *(float4*)(b0)     = *(const float4*)&Ys[kk][tx * 8];
            *(float4*)(b0 + 4) = *(const float4*)&Ys[kk][tx * 8 + 4];
#pragma unroll
            for (int r = 0; r < 8; ++r)
#pragma unroll
                for (int c = 0; c < 8; ++c)
                    acc[r][c] = fmaf(a0[r], b0[c], acc[r][c]);
        }
    }

#pragma unroll
    for (int r = 0; r < 8; ++r) {
        const int row = row0 + ty * 8 + r;
#pragma unroll
        for (int c4 = 0; c4 < 8; c4 += 4) {
            float4 v;
            float* vp = &v.x;
#pragma unroll
            for (int q = 0; q < 4; ++q) {
                const float x = acc[r][c4 + q];
                const float l = log1pf(__expf(-fabsf(x)));
                vp[q] = sel ? (fminf(x, 0.f) - l)     // log_sigmoid
                            : (fmaxf(x, 0.f) + l);    // softplus
            }
            *(float4*)(C + (size_t)row * M_ + col0 + tx * 8 + c4) = v;
        }
    }
}

// ---------------------------------------------------------------------------
// Diagonalize: theta,A (row-major) -> g_tha (diag-major float2, pre-scaled).
// ---------------------------------------------------------------------------
__global__ void __launch_bounds__(256) diag_kernel(const float* __restrict__ out)
{
    const float* theta = out + (size_t)B_ * N_ * M_;
    const float* Ag    = out + (size_t)2 * B_ * N_ * M_;
    const int b  = blockIdx.z;
    const int i0 = blockIdx.y * 32;
    const int j0 = blockIdx.x * 32;

    __shared__ float sth[32 * 32];
    __shared__ float sa [32 * 32];

    const int t    = threadIdx.x;
    const int warp = t >> 5;
    const int lane = t & 31;

#pragma unroll
    for (int it = 0; it < 4; ++it) {
        const int r = warp + it * 8;
        const int c = lane;
        const size_t g = ((size_t)b * N_ + (i0 + r)) * M_ + (j0 + c);
        sth[r * 32 + c] = theta[g] * INV_LN2;
        sa [r * 32 + c] = Ag[g]    * INV_LN2;
    }
    __syncthreads();

    float2* dst = g_tha + (size_t)b * ND_ * N_;
#pragma unroll
    for (int dd0 = 0; dd0 < 64; dd0 += 8) {
        const int dd = dd0 + warp;
        const int il = lane;
        const int jl = dd - il;
        if ((unsigned)jl < 32u) {
            const int d = i0 + j0 + dd;
            dst[(size_t)d * N_ + (i0 + il)] = make_float2(sth[il * 32 + jl], sa[il * 32 + jl]);
        }
    }
}

// ---------------------------------------------------------------------------
// Undiagonalize: g_e (diag-major) -> aln (row-major).
// ---------------------------------------------------------------------------
__global__ void __launch_bounds__(256) undiag_kernel(float* __restrict__ out)
{
    const int b  = blockIdx.z;
    const int i0 = blockIdx.y * 32;
    const int j0 = blockIdx.x * 32;

    __shared__ float se[32 * 32];

    const int t    = threadIdx.x;
    const int warp = t >> 5;
    const int lane = t & 31;

    const float* src = g_e + (size_t)b * ND_ * N_;
#pragma unroll
    for (int dd0 = 0; dd0 < 64; dd0 += 8) {
        const int dd = dd0 + warp;
        const int il = lane;
        const int jl = dd - il;
        if ((unsigned)jl < 32u) {
            const int d = i0 + j0 + dd;
            se[il * 32 + jl] = src[(size_t)d * N_ + (i0 + il)];
        }
    }
    __syncthreads();

    float* alnB = out + (size_t)b * N_ * M_;
#pragma unroll
    for (int it = 0; it < 4; ++it) {
        const int r = warp + it * 8;
        const int c = lane;
        alnB[(size_t)(i0 + r) * M_ + (j0 + c)] = se[r * 32 + c];
    }
}

// ---------------------------------------------------------------------------
// Forward soft-NW. Explicit register pointer rotation (no dynamic indexing),
// unconditional zero-padded loads, whole-warp band early-out.
// ---------------------------------------------------------------------------
__global__ void __launch_bounds__(512) nw_fwd_kernel()
{
    const int b   = blockIdx.x;
    const int tid = threadIdx.x;
    const int w0  = tid & ~31;

    __shared__ float s0[516], s1[516], s2[516];
    for (int idx = tid; idx < 516; idx += 512) { s0[idx] = NEGL; s1[idx] = NEGL; s2[idx] = NEGL; }
    __syncthreads();
    if (tid == 0) s0[0] = 0.f;     // diag k=0: V[0,0] = 0
    __syncthreads();

    float* p2 = s0;   // diag k-2
    float* p1 = s1;   // diag k-1
    float* pc = s2;   // diag k

    const float2* THA = g_tha + (size_t)b * ND_ * N_;
    float2*       Wb  = g_w   + (size_t)b * ND_ * N_;

    // depth-2 prefetch of (theta, A): invalid slots are zero in g_tha
    float2 t0 = THA[tid];
    float2 t1 = THA[(size_t)N_ + tid];

    const int bandHi = w0 + 32 + M_ - 1;

    for (int k = 2; k <= N_ + M_; ++k) {
        const int d  = k - 2;
        const int dn = d + 2;
        float2 tn = make_float2(0.f, 0.f);
        if (dn < ND_) tn = THA[(size_t)dn * N_ + tid];   // uniform guard

        if (d >= w0 && d < bandHi) {
            const float up = p1[tid];        // V[i-1, j]
            const float lf = p1[tid + 1];    // V[i,   j-1]
            const float dg = p2[tid];        // V[i-1, j-1]

            const float x0 = t0.y + up;
            const float x2 = t0.y + lf;
            const float m  = fmaxf(fmaxf(x0, x2), dg);
            const float e0 = ex2f_(x0 - m);
            const float e1 = ex2f_(dg - m);
            const float e2 = ex2f_(x2 - m);
            const float s  = e0 + e1 + e2;
            const float r  = rcpf_(s);
            const float v  = t0.x + m + lg2f_(s);

            const bool valid = (unsigned)(d - tid) < (unsigned)M_;
            pc[tid + 1] = valid ? v : NEGL;
            if (tid == 0) pc[0] = NEGL;
            Wb[(size_t)d * N_ + tid] = valid ? make_float2(e0 * r, e2 * r)
                                             : make_float2(0.f, 0.f);
        }
        t0 = t1; t1 = tn;
        float* tp = p2; p2 = p1; p1 = pc; pc = tp;
        __syncthreads();
    }
}

// ---------------------------------------------------------------------------
// Backward: E[i,j] = E[i+1,j]*wU(i+1,j) + E[i,j+1]*wL(i,j+1)
//                  + E[i+1,j+1]*(1-wU-wL)(i+1,j+1),  E[N,M]=1.
// One LDG (float2) per thread per iteration; W diagonals staged through a
// 3-buffer smem ring so neighbor weights come from LDS. No validity guards:
// invalid cells have zero weights in g_w.
// ---------------------------------------------------------------------------
__global__ void __launch_bounds__(512) nw_bwd_kernel()
{
    const int b   = blockIdx.x;
    const int tid = threadIdx.x;
    const int w0  = tid & ~31;

    __shared__ float  e0s[516], e1s[516], e2s[516];
    __shared__ float2 w0s[516], w1s[516], w2s[516];
    for (int idx = tid; idx < 516; idx += 512) {
        e0s[idx] = 0.f; e1s[idx] = 0.f; e2s[idx] = 0.f;
        w0s[idx] = make_float2(0.f, 0.f);
        w1s[idx] = make_float2(0.f, 0.f);
        w2s[idx] = make_float2(0.f, 0.f);
    }
    __syncthreads();

    float* cur = e0s;   // E diag k
    float* n1  = e1s;   // E diag k+1
    float* n2  = e2s;   // E diag k+2

    float2* sW0 = w0s;  // store target: W diag d
    float2* sW1 = w1s;  // W diag d+1 (zeros initially: diag 1023 doesn't exist)
    float2* sW2 = w2s;  // W diag d+2

    const float2* Wb = g_w + (size_t)b * ND_ * N_;
    float*        Eb = g_e + (size_t)b * ND_ * N_;

    // register queue of W diagonals: wq = diag d, wq1 = diag d-1
    float2 wprev = make_float2(0.f, 0.f);                 // diag d+1 (none yet)
    float2 wq  = Wb[(size_t)(ND_ - 1) * N_ + tid];        // diag 1022
    float2 wq1 = Wb[(size_t)(ND_ - 2) * N_ + tid];        // diag 1021

    const int bandHi = w0 + 32 + M_ - 1;

    for (int k = N_ + M_; k >= 2; --k) {
        const int d  = k - 2;
        const int dl = d - 2;
        float2 wq2 = make_float2(0.f, 0.f);
        if (dl >= 0) wq2 = Wb[(size_t)dl * N_ + tid];     // uniform guard

        sW0[tid] = wq;                                    // W diag d, for next iter

        if (d >= w0 && d < bandHi) {
            const float2 Aq = sW1[tid + 1];   // cell (i+1, j):   .x = wU
            const float2 Cq = sW2[tid + 1];   // cell (i+1, j+1): wD = 1-.x-.y
            // wprev == sW1[tid] == cell (i, j+1): .y = wL

            float e = n1[tid + 2] * Aq.x
                    + n1[tid + 1] * wprev.y
                    + n2[tid + 2] * (1.f - Cq.x - Cq.y);
            if (k == N_ + M_) e = 1.f;        // base case E[N,M]

            const bool valid = (unsigned)(d - tid) < (unsigned)M_;
            const float ev = valid ? e : 0.f;
            cur[tid + 1] = ev;
            Eb[(size_t)d * N_ + tid] = ev;
        }

        wprev = wq; wq = wq1; wq1 = wq2;
        float2* tw = sW2; sW2 = sW1; sW1 = sW0; sW0 = tw;
        float*  te = n2;  n2  = n1;  n1  = cur; cur = te;
        __syncthreads();
    }
}

// ---------------------------------------------------------------------------
// launch
// ---------------------------------------------------------------------------
extern "C" void kernel_launch(void* const* d_in, const int* in_sizes, int n_in,
                              void* d_out, int out_size)
{
    const float* zx = (const float*)d_in[0];
    const float* zy = (const float*)d_in[1];
    const float* gx = (const float*)d_in[2];
    const float* gy = (const float*)d_in[3];
    float* out = (float*)d_out;   // [aln | theta | A]

    dim3 ggrid(M_ / 128, N_ / 128, 2 * B_);
    gemm_act_kernel<<<ggrid, 256>>>(zx, zy, gx, gy, out);

    dim3 tgrid(M_ / 32, N_ / 32, B_);
    diag_kernel<<<tgrid, 256>>>(out);
    nw_fwd_kernel<<<B_, 512>>>();
    nw_bwd_kernel<<<B_, 512>>>();
    undiag_kernel<<<tgrid, 256>>>(out);
}